// round 8
// baseline (speedup 1.0000x reference)
#include <cuda_runtime.h>
#include <math.h>
#include <stdint.h>

#define NA 8400
#define NB 64
#define NC 80
#define KTOP 10
#define ASSIGN_BLOCKS NB
#define TOTAL_BLOCKS 1184         // 148 SMs x 8 blocks -> exactly one wave
#define STREAM_BLOCKS (TOTAL_BLOCKS - ASSIGN_BLOCKS)   // 1120
#define THREADS 256
#define MAXC 1536                 // max inside-anchors (worst case ~1073 for wh<=220)

// per-block partial sums (plain stores -> no init kernel, no hot-path atomics)
__device__ double g_pc[TOTAL_BLOCKS];   // cls partial
__device__ double g_pb[ASSIGN_BLOCKS];  // box partial
__device__ int    g_pn[ASSIGN_BLOCKS];  // npos partial
__device__ int    g_count;              // arrival ticket; last block resets to 0

__device__ __forceinline__ float fast_ex2(float x){ float y; asm("ex2.approx.f32 %0, %1;" : "=f"(y) : "f"(x)); return y; }
__device__ __forceinline__ float fast_lg2(float x){ float y; asm("lg2.approx.f32 %0, %1;" : "=f"(y) : "f"(x)); return y; }
__device__ __forceinline__ float fast_rcp(float x){ float y; asm("rcp.approx.f32 %0, %1;" : "=f"(y) : "f"(x)); return y; }

// focal at target 0, WITHOUT the 0.75 alpha factor: softplus(x) * sigmoid(x)^2
__device__ __forceinline__ float focal_zero_raw(float x){
    x = fmaxf(x, -87.0f);
    float v  = fast_ex2(-x * 1.44269504f);        // e^{-x}
    float w  = 1.0f + v;
    float r  = fast_rcp(w);                       // sigmoid(x)
    float ce = fmaf(fast_lg2(w), 0.69314718f, x); // softplus(x)
    return ce * r * r;
}

// exact-style focal for arbitrary target (cold path, <=640 evals)
__device__ __forceinline__ float focal_t(float x, float t){
    float p  = 1.0f / (1.0f + expf(-x));
    float ce = fmaxf(x, 0.0f) - x * t + log1pf(expf(-fabsf(x)));
    float pt = p * t + (1.0f - p) * (1.0f - t);
    float at = 0.25f * t + 0.75f * (1.0f - t);
    float om = 1.0f - pt;
    return at * ce * om * om;
}

__device__ __forceinline__ void anchor_of(int a, float& ax, float& ay, float& st){
    if (a < 6400){
        int gy = a / 80, gx = a - gy * 80;
        ax = (gx + 0.5f) * 8.0f; ay = (gy + 0.5f) * 8.0f; st = 8.0f;
    } else if (a < 8000){
        int i = a - 6400; int gy = i / 40, gx = i - gy * 40;
        ax = (gx + 0.5f) * 16.0f; ay = (gy + 0.5f) * 16.0f; st = 16.0f;
    } else {
        int i = a - 8000; int gy = i / 20, gx = i - gy * 20;
        ax = (gx + 0.5f) * 32.0f; ay = (gy + 0.5f) * 32.0f; st = 32.0f;
    }
}

__device__ __forceinline__ void decode_box(float4 pb, float ax, float ay, float st,
                                           float& x1, float& y1, float& x2, float& y2){
    float d0 = fmaxf(pb.x, 0.0f) * st;
    float d1 = fmaxf(pb.y, 0.0f) * st;
    float d2 = fmaxf(pb.z, 0.0f) * st;
    float d3 = fmaxf(pb.w, 0.0f) * st;
    x1 = ax - d0; y1 = ay - d1; x2 = ax + d2; y2 = ay + d3;
}

__device__ __forceinline__ float iou_vs_gt(float x1, float y1, float x2, float y2,
                                           float gx1, float gy1, float gx2, float gy2){
    float iw = fmaxf(fminf(x2, gx2) - fmaxf(x1, gx1), 0.0f);
    float ih = fmaxf(fminf(y2, gy2) - fmaxf(y1, gy1), 0.0f);
    float inter = iw * ih;
    float a1 = (x2 - x1) * (y2 - y1);
    float a2 = (gx2 - gx1) * (gy2 - gy1);
    return inter / (a1 + a2 - inter);
}

__device__ __forceinline__ float ciou_term(float x1, float y1, float x2, float y2,
                                           float gx1, float gy1, float gx2, float gy2){
    const float E = 1e-7f;
    float w1 = x2 - x1, h1 = y2 - y1;
    float w2 = gx2 - gx1, h2 = gy2 - gy1;
    float iw = fmaxf(fminf(x2, gx2) - fmaxf(x1, gx1), 0.0f);
    float ih = fmaxf(fminf(y2, gy2) - fmaxf(y1, gy1), 0.0f);
    float inter = iw * ih;
    float uni = w1 * h1 + w2 * h2 - inter + E;
    float iou = inter / uni;
    float cw = fmaxf(x2, gx2) - fminf(x1, gx1);
    float ch = fmaxf(y2, gy2) - fminf(y1, gy1);
    float c2 = cw * cw + ch * ch + E;
    float dx = gx1 + gx2 - x1 - x2;
    float dy = gy1 + gy2 - y1 - y2;
    float rho2 = (dx * dx + dy * dy) * 0.25f;
    float dat = atanf(w2 / (h2 + E)) - atanf(w1 / (h1 + E));
    float v = 0.4052847345693511f * dat * dat;   // 4/pi^2
    float alpha = v / (v - iou + (1.0f + E));
    return 1.0f - iou + rho2 / c2 + alpha * v;
}

// compute metric for one candidate anchor (gathers box + class logit)
__device__ __forceinline__ float metric_of(int a, const float4* pbb, const float* psb,
                                           float gx1, float gy1, float gx2, float gy2){
    float ax, ay, st; anchor_of(a, ax, ay, st);
    float4 pb = pbb[a];
    float x1, y1, x2, y2; decode_box(pb, ax, ay, st, x1, y1, x2, y2);
    float iou = fmaxf(iou_vs_gt(x1, y1, x2, y2, gx1, gy1, gx2, gy2), 1e-9f);
    float lg = psb[(size_t)a * NC];
    float cls = 1.0f / (1.0f + expf(-lg));
    float i2 = iou * iou;
    return sqrtf(cls) * i2 * i2 * i2;
}

// ============ cold path: assignment for one batch image (noinline isolates regs) ============
__device__ __noinline__ void assign_image(int b, int tid,
                                          const float* __restrict__ pred_boxes,
                                          const float* __restrict__ pred_scores,
                                          const float* __restrict__ gt_bboxes,
                                          const int*   __restrict__ gt_labels,
                                          float* s_vals, int* s_idx,
                                          float* s_rv, int* s_ri,
                                          float* s_topv, int* s_topi,
                                          int* s_cnt)
{
    const float gcx = gt_bboxes[b * 4 + 0], gcy = gt_bboxes[b * 4 + 1];
    const float gw  = gt_bboxes[b * 4 + 2], gh  = gt_bboxes[b * 4 + 3];
    const float gx1 = gcx - gw * 0.5f, gy1 = gcy - gh * 0.5f;
    const float gx2 = gcx + gw * 0.5f, gy2 = gcy + gh * 0.5f;
    const bool  valid = (gx2 > gx1) && (gy2 > gy1);
    const int   label = gt_labels[b];
    const float gcenx = (gx1 + gx2) * 0.5f, gceny = (gy1 + gy2) * 0.5f;

    const float4* pbb = (const float4*)(pred_boxes + (size_t)b * NA * 4);
    const float*  psb = pred_scores + (size_t)b * NA * NC + label;

    if (tid == 0) *s_cnt = 0;
    __syncthreads();

    // pass 1: inside test from anchor coords only; compact candidates; track argmin dist
    float mind = INFINITY; int mini = 0;
    for (int a = tid; a < NA; a += THREADS) {
        float ax, ay, st; anchor_of(a, ax, ay, st);
        bool inside = (ax >= gx1) && (ax <= gx2) && (ay >= gy1) && (ay <= gy2);
        float dx = ax - gcenx, dy = ay - gceny;
        float dist = dx * dx + dy * dy;
        if (dist < mind || (dist == mind && a < mini)) { mind = dist; mini = a; }
        if (inside) {
            int slot = atomicAdd(s_cnt, 1);
            if (slot < MAXC) {
                s_vals[slot] = metric_of(a, pbb, psb, gx1, gy1, gx2, gy2);
                s_idx[slot]  = a;
            }
        }
    }
    s_rv[tid] = mind; s_ri[tid] = mini;
    __syncthreads();
    // lexicographic argmin (dist asc, index asc) — matches jnp.argmin tie-break
    for (int off = THREADS / 2; off > 0; off >>= 1) {
        if (tid < off) {
            float ov = s_rv[tid + off]; int oi = s_ri[tid + off];
            if (ov < s_rv[tid] || (ov == s_rv[tid] && oi < s_ri[tid])) { s_rv[tid] = ov; s_ri[tid] = oi; }
        }
        __syncthreads();
    }
    int count = min(*s_cnt, MAXC);
    if (count == 0 && tid == 0) {
        // fallback: nearest anchor is the single candidate (mask = one-hot)
        int fb = s_ri[0];
        s_vals[0] = metric_of(fb, pbb, psb, gx1, gy1, gx2, gy2);
        s_idx[0]  = fb;
        *s_cnt = 1;
    }
    __syncthreads();
    count = min(*s_cnt, MAXC);

    // top-K by repeated block argmax (value desc, index asc) — matches lax.top_k
    for (int r = 0; r < KTOP; r++) {
        float bv = -INFINITY; int bi = 0x7fffffff;
        for (int i = tid; i < count; i += THREADS) {
            float v = s_vals[i]; int a = s_idx[i];
            if (v > bv || (v == bv && a < bi)) { bv = v; bi = a; }
        }
        s_rv[tid] = bv; s_ri[tid] = bi;
        __syncthreads();
        for (int off = THREADS / 2; off > 0; off >>= 1) {
            if (tid < off) {
                float ov = s_rv[tid + off]; int oi = s_ri[tid + off];
                if (ov > s_rv[tid] || (ov == s_rv[tid] && oi < s_ri[tid])) { s_rv[tid] = ov; s_ri[tid] = oi; }
            }
            __syncthreads();
        }
        if (tid == 0) {
            s_topv[r] = s_rv[0]; s_topi[r] = s_ri[0];
            if (s_rv[0] != -INFINITY) {
                // invalidate the winner in the candidate list
                for (int i = 0; i < count; i++) { if (s_idx[i] == s_ri[0]) { s_vals[i] = -INFINITY; break; } }
            }
        }
        __syncthreads();
    }

    // per-selected-anchor: focal correction (target = iou) + CIoU box loss + npos
    float corr = 0.0f, cl = 0.0f; int np = 0;
    if (tid < KTOP) {
        float mv = s_topv[tid];
        if (valid && mv != -INFINITY) {
            int a = s_topi[tid];
            float ax, ay, st; anchor_of(a, ax, ay, st);
            float4 pb = pbb[a];
            float x1, y1, x2, y2; decode_box(pb, ax, ay, st, x1, y1, x2, y2);
            float iou = fmaxf(iou_vs_gt(x1, y1, x2, y2, gx1, gy1, gx2, gy2), 1e-9f);
            float lgt = psb[(size_t)a * NC];
            corr = focal_t(lgt, iou) - 0.75f * focal_zero_raw(lgt);
            cl = ciou_term(x1, y1, x2, y2, gx1, gy1, gx2, gy2);
            np = 1;
        }
    }
    s_rv[tid] = (tid < KTOP) ? corr : 0.0f;
    s_ri[tid] = (tid < KTOP) ? np : 0;
    __syncthreads();
    if (tid == 0) {
        double csum = 0.0; int nsum = 0;
        for (int i = 0; i < KTOP; i++) { csum += (double)s_rv[i]; nsum += s_ri[i]; }
        g_pc[b] = csum;
        g_pn[b] = nsum;
    }
    __syncthreads();
    s_rv[tid] = (tid < KTOP) ? cl : 0.0f;
    __syncthreads();
    if (tid == 0) {
        double bsum = 0.0;
        for (int i = 0; i < KTOP; i++) bsum += (double)s_rv[i];
        g_pb[b] = bsum;
    }
}

__global__ __launch_bounds__(THREADS, 8)
void yolo_main_kernel(const float* __restrict__ pred_boxes,
                      const float* __restrict__ pred_scores,
                      const float* __restrict__ gt_bboxes,
                      const int*   __restrict__ gt_labels,
                      float* __restrict__ out)
{
    __shared__ float s_vals[MAXC];
    __shared__ int   s_idx[MAXC];
    __shared__ float s_rv[THREADS];
    __shared__ int   s_ri[THREADS];
    __shared__ float s_topv[KTOP];
    __shared__ int   s_topi[KTOP];
    __shared__ int   s_cnt;
    __shared__ int   s_last;

    const int blk = blockIdx.x;
    const int tid = threadIdx.x;

    if (blk < ASSIGN_BLOCKS) {
        assign_image(blk, tid, pred_boxes, pred_scores, gt_bboxes, gt_labels,
                     s_vals, s_idx, s_rv, s_ri, s_topv, s_topi, &s_cnt);
    } else {
        // ===================== streaming focal(target=0) over all logits =====================
        const float4* ps4 = (const float4*)pred_scores;
        const int total4 = (NB * NA * NC) / 4;          // 10,752,000
        const int sb = blk - ASSIGN_BLOCKS;
        const int stride = STREAM_BLOCKS * THREADS;
        float a0 = 0.0f, a1 = 0.0f, a2 = 0.0f, a3 = 0.0f;
        #pragma unroll 2
        for (int i = sb * THREADS + tid; i < total4; i += stride) {
            float4 v = __ldcs(&ps4[i]);   // streaming: no reuse, evict-first
            a0 += focal_zero_raw(v.x);
            a1 += focal_zero_raw(v.y);
            a2 += focal_zero_raw(v.z);
            a3 += focal_zero_raw(v.w);
        }
        s_rv[tid] = (a0 + a1) + (a2 + a3);
        __syncthreads();
        for (int off = THREADS / 2; off > 0; off >>= 1) {
            if (tid < off) s_rv[tid] += s_rv[tid + off];
            __syncthreads();
        }
        if (tid == 0) g_pc[blk] = (double)s_rv[0] * 0.75;
    }

    // ===================== fused finale: last block to arrive reduces everything =====================
    __threadfence();
    if (tid == 0) {
        int prev = atomicAdd(&g_count, 1);
        s_last = (prev == TOTAL_BLOCKS - 1);
    }
    __syncthreads();
    if (!s_last) return;

    {
        __shared__ double f_c[THREADS];
        __shared__ double f_b[THREADS];
        __shared__ int    f_n[THREADS];
        double c = 0.0, bx = 0.0; int n = 0;
        for (int i = tid; i < TOTAL_BLOCKS; i += THREADS) c += g_pc[i];
        if (tid < ASSIGN_BLOCKS) { bx = g_pb[tid]; n = g_pn[tid]; }
        f_c[tid] = c; f_b[tid] = bx; f_n[tid] = n;
        __syncthreads();
        for (int off = THREADS / 2; off > 0; off >>= 1) {
            if (tid < off) { f_c[tid] += f_c[tid + off]; f_b[tid] += f_b[tid + off]; f_n[tid] += f_n[tid + off]; }
            __syncthreads();
        }
        if (tid == 0) {
            double npos = (double)max(f_n[0], 1);
            out[0] = (float)(f_c[0] / npos + 2.5 * f_b[0] / npos);
            g_count = 0;                   // reset ticket for next graph replay
        }
    }
}

extern "C" void kernel_launch(void* const* d_in, const int* in_sizes, int n_in,
                              void* d_out, int out_size)
{
    const float* pred_boxes  = (const float*)d_in[0];
    const float* pred_scores = (const float*)d_in[1];
    const float* gt_bboxes   = (const float*)d_in[2];
    const int*   gt_labels   = (const int*)d_in[3];
    float* out = (float*)d_out;

    yolo_main_kernel<<<TOTAL_BLOCKS, THREADS>>>(pred_boxes, pred_scores, gt_bboxes, gt_labels, out);
}

// round 9
// speedup vs baseline: 8.6125x; 8.6125x over previous
#include <cuda_runtime.h>
#include <math.h>
#include <stdint.h>

#define NA 8400
#define NB 64
#define NC 80
#define KTOP 10
#define ASSIGN_BLOCKS NB
#define TOTAL_BLOCKS 1184         // 148 SMs x 8 blocks -> exactly one wave
#define STREAM_BLOCKS (TOTAL_BLOCKS - ASSIGN_BLOCKS)   // 1120
#define THREADS 256
#define MAXC 1536                 // max inside-anchors (worst case ~1073 for wh<=220)

// per-block partial sums (plain stores -> no init kernel, no hot-path atomics)
__device__ double g_pc[TOTAL_BLOCKS];   // cls partial
__device__ double g_pb[ASSIGN_BLOCKS];  // box partial
__device__ int    g_pn[ASSIGN_BLOCKS];  // npos partial
__device__ int    g_count;              // arrival ticket; last block resets to 0

__device__ __forceinline__ float fast_ex2(float x){ float y; asm("ex2.approx.f32 %0, %1;" : "=f"(y) : "f"(x)); return y; }
__device__ __forceinline__ float fast_lg2(float x){ float y; asm("lg2.approx.f32 %0, %1;" : "=f"(y) : "f"(x)); return y; }
__device__ __forceinline__ float fast_rcp(float x){ float y; asm("rcp.approx.f32 %0, %1;" : "=f"(y) : "f"(x)); return y; }

// focal at target 0, WITHOUT the 0.75 alpha factor: softplus(x) * sigmoid(x)^2
__device__ __forceinline__ float focal_zero_raw(float x){
    x = fmaxf(x, -87.0f);
    float v  = fast_ex2(-x * 1.44269504f);        // e^{-x}
    float w  = 1.0f + v;
    float r  = fast_rcp(w);                       // sigmoid(x)
    float ce = fmaf(fast_lg2(w), 0.69314718f, x); // softplus(x)
    return ce * r * r;
}

// exact-style focal for arbitrary target (cold path, <=640 evals)
__device__ __forceinline__ float focal_t(float x, float t){
    float p  = 1.0f / (1.0f + expf(-x));
    float ce = fmaxf(x, 0.0f) - x * t + log1pf(expf(-fabsf(x)));
    float pt = p * t + (1.0f - p) * (1.0f - t);
    float at = 0.25f * t + 0.75f * (1.0f - t);
    float om = 1.0f - pt;
    return at * ce * om * om;
}

// monotonic float->uint mapping (preserves total order, incl. -inf)
__device__ __forceinline__ unsigned flip_f(float v){
    unsigned b = __float_as_uint(v);
    return (b & 0x80000000u) ? ~b : (b | 0x80000000u);
}
__device__ __forceinline__ float unflip_f(unsigned f){
    unsigned b = (f & 0x80000000u) ? (f ^ 0x80000000u) : ~f;
    return __uint_as_float(b);
}

__device__ __forceinline__ void anchor_of(int a, float& ax, float& ay, float& st){
    if (a < 6400){
        int gy = a / 80, gx = a - gy * 80;
        ax = (gx + 0.5f) * 8.0f; ay = (gy + 0.5f) * 8.0f; st = 8.0f;
    } else if (a < 8000){
        int i = a - 6400; int gy = i / 40, gx = i - gy * 40;
        ax = (gx + 0.5f) * 16.0f; ay = (gy + 0.5f) * 16.0f; st = 16.0f;
    } else {
        int i = a - 8000; int gy = i / 20, gx = i - gy * 20;
        ax = (gx + 0.5f) * 32.0f; ay = (gy + 0.5f) * 32.0f; st = 32.0f;
    }
}

__device__ __forceinline__ void decode_box(float4 pb, float ax, float ay, float st,
                                           float& x1, float& y1, float& x2, float& y2){
    float d0 = fmaxf(pb.x, 0.0f) * st;
    float d1 = fmaxf(pb.y, 0.0f) * st;
    float d2 = fmaxf(pb.z, 0.0f) * st;
    float d3 = fmaxf(pb.w, 0.0f) * st;
    x1 = ax - d0; y1 = ay - d1; x2 = ax + d2; y2 = ay + d3;
}

__device__ __forceinline__ float iou_vs_gt(float x1, float y1, float x2, float y2,
                                           float gx1, float gy1, float gx2, float gy2){
    float iw = fmaxf(fminf(x2, gx2) - fmaxf(x1, gx1), 0.0f);
    float ih = fmaxf(fminf(y2, gy2) - fmaxf(y1, gy1), 0.0f);
    float inter = iw * ih;
    float a1 = (x2 - x1) * (y2 - y1);
    float a2 = (gx2 - gx1) * (gy2 - gy1);
    return inter / (a1 + a2 - inter);
}

__device__ __forceinline__ float ciou_term(float x1, float y1, float x2, float y2,
                                           float gx1, float gy1, float gx2, float gy2){
    const float E = 1e-7f;
    float w1 = x2 - x1, h1 = y2 - y1;
    float w2 = gx2 - gx1, h2 = gy2 - gy1;
    float iw = fmaxf(fminf(x2, gx2) - fmaxf(x1, gx1), 0.0f);
    float ih = fmaxf(fminf(y2, gy2) - fmaxf(y1, gy1), 0.0f);
    float inter = iw * ih;
    float uni = w1 * h1 + w2 * h2 - inter + E;
    float iou = inter / uni;
    float cw = fmaxf(x2, gx2) - fminf(x1, gx1);
    float ch = fmaxf(y2, gy2) - fminf(y1, gy1);
    float c2 = cw * cw + ch * ch + E;
    float dx = gx1 + gx2 - x1 - x2;
    float dy = gy1 + gy2 - y1 - y2;
    float rho2 = (dx * dx + dy * dy) * 0.25f;
    float dat = atanf(w2 / (h2 + E)) - atanf(w1 / (h1 + E));
    float v = 0.4052847345693511f * dat * dat;   // 4/pi^2
    float alpha = v / (v - iou + (1.0f + E));
    return 1.0f - iou + rho2 / c2 + alpha * v;
}

// compute metric for one candidate anchor (gathers box + class logit)
__device__ __forceinline__ float metric_of(int a, const float4* pbb, const float* psb,
                                           float gx1, float gy1, float gx2, float gy2){
    float ax, ay, st; anchor_of(a, ax, ay, st);
    float4 pb = pbb[a];
    float x1, y1, x2, y2; decode_box(pb, ax, ay, st, x1, y1, x2, y2);
    float iou = fmaxf(iou_vs_gt(x1, y1, x2, y2, gx1, gy1, gx2, gy2), 1e-9f);
    float lg = psb[(size_t)a * NC];
    float cls = 1.0f / (1.0f + expf(-lg));
    float i2 = iou * iou;
    return sqrtf(cls) * i2 * i2 * i2;
}

// ============ cold path: assignment for one batch image (noinline isolates regs) ============
__device__ __noinline__ void assign_image(int b, int tid,
                                          const float* __restrict__ pred_boxes,
                                          const float* __restrict__ pred_scores,
                                          const float* __restrict__ gt_bboxes,
                                          const int*   __restrict__ gt_labels,
                                          float* s_vals, int* s_idx,
                                          unsigned long long* s_key,
                                          float* s_topv, int* s_topi,
                                          int* s_cnt)
{
    const float gcx = gt_bboxes[b * 4 + 0], gcy = gt_bboxes[b * 4 + 1];
    const float gw  = gt_bboxes[b * 4 + 2], gh  = gt_bboxes[b * 4 + 3];
    const float gx1 = gcx - gw * 0.5f, gy1 = gcy - gh * 0.5f;
    const float gx2 = gcx + gw * 0.5f, gy2 = gcy + gh * 0.5f;
    const bool  valid = (gx2 > gx1) && (gy2 > gy1);
    const int   label = gt_labels[b];
    const float gcenx = (gx1 + gx2) * 0.5f, gceny = (gy1 + gy2) * 0.5f;

    const float4* pbb = (const float4*)(pred_boxes + (size_t)b * NA * 4);
    const float*  psb = pred_scores + (size_t)b * NA * NC + label;

    if (tid == 0) *s_cnt = 0;
    __syncthreads();

    // pass 1: inside test from anchor coords only; compact candidates; track argmin dist
    // argmin carried as u64 key: (flip(dist) << 32) | anchor  -> min-reduce = (dist asc, index asc)
    unsigned long long dkey = ~0ull;
    for (int a = tid; a < NA; a += THREADS) {
        float ax, ay, st; anchor_of(a, ax, ay, st);
        bool inside = (ax >= gx1) && (ax <= gx2) && (ay >= gy1) && (ay <= gy2);
        float dx = ax - gcenx, dy = ay - gceny;
        float dist = dx * dx + dy * dy;
        unsigned long long k = ((unsigned long long)flip_f(dist) << 32) | (unsigned)a;
        dkey = min(dkey, k);
        if (inside) {
            int slot = atomicAdd(s_cnt, 1);
            if (slot < MAXC) {
                s_vals[slot] = metric_of(a, pbb, psb, gx1, gy1, gx2, gy2);
                s_idx[slot]  = a;
            }
        }
    }
    s_key[tid] = dkey;
    __syncthreads();
    for (int off = THREADS / 2; off > 0; off >>= 1) {
        if (tid < off) s_key[tid] = min(s_key[tid], s_key[tid + off]);
        __syncthreads();
    }
    int count = min(*s_cnt, MAXC);
    if (count == 0 && tid == 0) {
        // fallback: nearest anchor is the single candidate (mask = one-hot)
        int fb = (int)(s_key[0] & 0xFFFFFFFFu);
        s_vals[0] = metric_of(fb, pbb, psb, gx1, gy1, gx2, gy2);
        s_idx[0]  = fb;
        *s_cnt = 1;
    }
    __syncthreads();
    count = min(*s_cnt, MAXC);

    // top-K: per-round branchless u64 argmax (value desc, anchor asc), parallel invalidation
    for (int r = 0; r < KTOP; r++) {
        unsigned long long best = 0ull;
        for (int i = tid; i < count; i += THREADS) {
            unsigned long long k = ((unsigned long long)flip_f(s_vals[i]) << 32)
                                 | (unsigned)(0x7FFFFFFF - s_idx[i]);
            best = max(best, k);
        }
        s_key[tid] = best;
        __syncthreads();
        for (int off = THREADS / 2; off > 0; off >>= 1) {
            if (tid < off) s_key[tid] = max(s_key[tid], s_key[tid + off]);
            __syncthreads();
        }
        unsigned long long wk = s_key[0];
        int   wa = 0x7FFFFFFF - (int)(wk & 0xFFFFFFFFu);
        float wv = unflip_f((unsigned)(wk >> 32));
        if (tid == 0) { s_topv[r] = wv; s_topi[r] = wa; }
        // parallel invalidation of the winner's slot
        for (int i = tid; i < count; i += THREADS)
            if (s_idx[i] == wa) s_vals[i] = -INFINITY;
        __syncthreads();
    }

    // per-selected-anchor: focal correction (target = iou) + CIoU box loss + npos
    float corr = 0.0f, cl = 0.0f; int np = 0;
    if (tid < KTOP) {
        float mv = s_topv[tid];
        if (valid && mv != -INFINITY) {
            int a = s_topi[tid];
            float ax, ay, st; anchor_of(a, ax, ay, st);
            float4 pb = pbb[a];
            float x1, y1, x2, y2; decode_box(pb, ax, ay, st, x1, y1, x2, y2);
            float iou = fmaxf(iou_vs_gt(x1, y1, x2, y2, gx1, gy1, gx2, gy2), 1e-9f);
            float lgt = psb[(size_t)a * NC];
            corr = focal_t(lgt, iou) - 0.75f * focal_zero_raw(lgt);
            cl = ciou_term(x1, y1, x2, y2, gx1, gy1, gx2, gy2);
            np = 1;
        }
    }
    // reduce the <=KTOP contributions via smem (reuse s_vals/s_idx)
    s_vals[tid] = (tid < KTOP) ? corr : 0.0f;
    s_idx[tid]  = (tid < KTOP) ? np : 0;
    s_vals[THREADS + tid] = (tid < KTOP) ? cl : 0.0f;
    __syncthreads();
    if (tid == 0) {
        double csum = 0.0, bsum = 0.0; int nsum = 0;
        for (int i = 0; i < KTOP; i++) {
            csum += (double)s_vals[i];
            bsum += (double)s_vals[THREADS + i];
            nsum += s_idx[i];
        }
        g_pc[b] = csum;
        g_pb[b] = bsum;
        g_pn[b] = nsum;
    }
}

__global__ __launch_bounds__(THREADS, 8)
void yolo_main_kernel(const float* __restrict__ pred_boxes,
                      const float* __restrict__ pred_scores,
                      const float* __restrict__ gt_bboxes,
                      const int*   __restrict__ gt_labels,
                      float* __restrict__ out)
{
    __shared__ float s_vals[MAXC];
    __shared__ int   s_idx[MAXC];
    __shared__ unsigned long long s_key[THREADS];
    __shared__ float s_topv[KTOP];
    __shared__ int   s_topi[KTOP];
    __shared__ int   s_cnt;
    __shared__ int   s_last;

    const int blk = blockIdx.x;
    const int tid = threadIdx.x;

    if (blk < ASSIGN_BLOCKS) {
        assign_image(blk, tid, pred_boxes, pred_scores, gt_bboxes, gt_labels,
                     s_vals, s_idx, s_key, s_topv, s_topi, &s_cnt);
    } else {
        // ===================== streaming focal(target=0) over all logits =====================
        const float4* ps4 = (const float4*)pred_scores;
        const int total4 = (NB * NA * NC) / 4;          // 10,752,000
        const int sb = blk - ASSIGN_BLOCKS;
        const int stride = STREAM_BLOCKS * THREADS;
        float a0 = 0.0f, a1 = 0.0f, a2 = 0.0f, a3 = 0.0f;
        #pragma unroll 2
        for (int i = sb * THREADS + tid; i < total4; i += stride) {
            float4 v = __ldcs(&ps4[i]);   // streaming: no reuse, evict-first
            a0 += focal_zero_raw(v.x);
            a1 += focal_zero_raw(v.y);
            a2 += focal_zero_raw(v.z);
            a3 += focal_zero_raw(v.w);
        }
        s_vals[tid] = (a0 + a1) + (a2 + a3);
        __syncthreads();
        for (int off = THREADS / 2; off > 0; off >>= 1) {
            if (tid < off) s_vals[tid] += s_vals[tid + off];
            __syncthreads();
        }
        if (tid == 0) g_pc[blk] = (double)s_vals[0] * 0.75;
    }

    // ===================== fused finale: last block to arrive reduces everything =====================
    __threadfence();
    if (tid == 0) {
        int prev = atomicAdd(&g_count, 1);
        s_last = (prev == TOTAL_BLOCKS - 1);
    }
    __syncthreads();
    if (!s_last) return;

    {
        __shared__ double f_c[THREADS];
        __shared__ double f_b[THREADS];
        __shared__ int    f_n[THREADS];
        double c = 0.0, bx = 0.0; int n = 0;
        for (int i = tid; i < TOTAL_BLOCKS; i += THREADS) c += g_pc[i];
        if (tid < ASSIGN_BLOCKS) { bx = g_pb[tid]; n = g_pn[tid]; }
        f_c[tid] = c; f_b[tid] = bx; f_n[tid] = n;
        __syncthreads();
        for (int off = THREADS / 2; off > 0; off >>= 1) {
            if (tid < off) { f_c[tid] += f_c[tid + off]; f_b[tid] += f_b[tid + off]; f_n[tid] += f_n[tid + off]; }
            __syncthreads();
        }
        if (tid == 0) {
            double npos = (double)max(f_n[0], 1);
            out[0] = (float)(f_c[0] / npos + 2.5 * f_b[0] / npos);
            g_count = 0;                   // reset ticket for next graph replay
        }
    }
}

extern "C" void kernel_launch(void* const* d_in, const int* in_sizes, int n_in,
                              void* d_out, int out_size)
{
    const float* pred_boxes  = (const float*)d_in[0];
    const float* pred_scores = (const float*)d_in[1];
    const float* gt_bboxes   = (const float*)d_in[2];
    const int*   gt_labels   = (const int*)d_in[3];
    float* out = (float*)d_out;

    yolo_main_kernel<<<TOTAL_BLOCKS, THREADS>>>(pred_boxes, pred_scores, gt_bboxes, gt_labels, out);
}